// round 6
// baseline (speedup 1.0000x reference)
#include <cuda_runtime.h>
#include <stdint.h>
#include <math.h>

#define BB 512
#define EE 256
#define HH 512
#define GG 1536
#define VV 32000
#define SS 256
#define OUT_LP_OFF (BB*SS) // 131072

#define NBLK 148
#define NTHR 512
#define NCH 4              // v-chunks per row in sampling phases
#define CHSZ (VV / NCH)    // 8000

// ---------------- scratch (device globals; no allocation allowed) ----------------
__device__ float g_h[BB * HH];
__device__ float g_gi[BB * GG];
__device__ float g_gh[BB * GG];
__device__ float g_logits[BB * VV];
__device__ int   g_sampled[BB];
__device__ float g_pm[BB * NCH];      // partial row max per (row, chunk)
__device__ float g_ps[BB * NCH];      // partial scaled expsum per (row, chunk)
__device__ float g_bv[BB * NCH];      // partial best value per (row, chunk)
__device__ int   g_bi[BB * NCH];      // partial best index
__device__ unsigned g_bar;

// ---------------- JAX threefry2x32 (exact) ----------------
__device__ __forceinline__ void tf2x32(uint32_t k0, uint32_t k1,
                                       uint32_t x0, uint32_t x1,
                                       uint32_t &o0, uint32_t &o1) {
  uint32_t k2 = k0 ^ k1 ^ 0x1BD11BDAu;
#define ROTL(x, r) (((x) << (r)) | ((x) >> (32 - (r))))
#define RND(r) { x0 += x1; x1 = ROTL(x1, r); x1 ^= x0; }
  x0 += k0; x1 += k1;
  RND(13) RND(15) RND(26) RND(6)
  x0 += k1; x1 += k2 + 1u;
  RND(17) RND(29) RND(16) RND(24)
  x0 += k2; x1 += k0 + 2u;
  RND(13) RND(15) RND(26) RND(6)
  x0 += k0; x1 += k1 + 3u;
  RND(17) RND(29) RND(16) RND(24)
  x0 += k1; x1 += k2 + 4u;
  RND(13) RND(15) RND(26) RND(6)
  x0 += k2; x1 += k0 + 5u;
#undef RND
#undef ROTL
  o0 = x0; o1 = x1;
}

// partitionable-mode: split(key,n)[i] = full output of threefry(key,(0,i))
__device__ __forceinline__ void split_key(uint32_t k0, uint32_t k1, uint32_t i,
                                          uint32_t &n0, uint32_t &n1) {
  tf2x32(k0, k1, 0u, i, n0, n1);
}

// random_bits(key,32,shape)[n] = o0 ^ o1 of threefry(key,(0,n))
__device__ __forceinline__ uint32_t rbits32(uint32_t k0, uint32_t k1, uint32_t n) {
  uint32_t o0, o1;
  tf2x32(k0, k1, 0u, n, o0, o1);
  return o0 ^ o1;
}

__device__ __forceinline__ float bits_to_uniform(uint32_t bits) {
  return __uint_as_float((bits >> 9) | 0x3f800000u) - 1.0f;
}

__device__ __forceinline__ float gumbel_from_bits(uint32_t bits) {
  float u = bits_to_uniform(bits);
  if (u == 0.0f) u = 1.17549435e-38f;   // uniform(minval=tiny): 0 -> tiny
  return -logf(-logf(u));               // accurate: argmax-critical
}

// ---------------- software grid barrier (monotonic target) ----------------
__device__ __forceinline__ void gridbar(unsigned &target) {
  target += NBLK;
  __syncthreads();
  if (threadIdx.x == 0) {
    __threadfence();
    atomicAdd(&g_bar, 1u);
    unsigned v;
    do {
      asm volatile("ld.acquire.gpu.u32 %0, [%1];" : "=r"(v) : "l"(&g_bar) : "memory");
    } while (v < target);
  }
  __syncthreads();
}

// ---------------- 128x128 fp32 TN GEMM tile, double-buffered, 512 threads ------
// Per-element accumulation: single serial fmaf chain over ascending k
// (k0 steps of 16, kk 0..15) -> bit-identical to the R5 kernel's outputs.
__device__ __forceinline__ void gemm128(
    const float *__restrict__ Abase, int aStride, const int *gather,
    int Krun, const float *__restrict__ W, int wStride,
    const float *__restrict__ bias, float *__restrict__ C, int ldc,
    int bm, int bn, float *sm) {
  float (*As)[16][132] = reinterpret_cast<float (*)[16][132]>(sm);
  float (*Ws)[16][132] = reinterpret_cast<float (*)[16][132]>(sm + 2 * 16 * 132);
  const int tid = threadIdx.x;
  const int tx = tid & 31;        // n group: cols tx*4 .. +3
  const int ty = tid >> 5;        // m group: rows ty*8 .. +7
  const int lr = tid >> 2;        // loader row/col 0..127
  const int lk = (tid & 3) * 4;   // loader k quad

  const int arowi = gather ? gather[bm + lr] : (bm + lr);
  const float *arow = Abase + (size_t)arowi * aStride;
  const float *wrow = W + (size_t)(bn + lr) * wStride;

  float acc[8][4];
#pragma unroll
  for (int i = 0; i < 8; i++)
#pragma unroll
    for (int j = 0; j < 4; j++) acc[i][j] = 0.0f;

  // preload k-tile 0 into buffer 0
  {
    float4 av = *reinterpret_cast<const float4 *>(arow + lk);
    float4 wv = *reinterpret_cast<const float4 *>(wrow + lk);
    As[0][lk + 0][lr] = av.x; As[0][lk + 1][lr] = av.y;
    As[0][lk + 2][lr] = av.z; As[0][lk + 3][lr] = av.w;
    Ws[0][lk + 0][lr] = wv.x; Ws[0][lk + 1][lr] = wv.y;
    Ws[0][lk + 2][lr] = wv.z; Ws[0][lk + 3][lr] = wv.w;
  }
  __syncthreads();

  const int nk = Krun >> 4;
#pragma unroll 1
  for (int kt = 0; kt < nk; kt++) {
    const int cur = kt & 1;
    float4 av, wv;
    const bool more = (kt + 1 < nk);
    if (more) {
      int k0 = (kt + 1) << 4;
      av = *reinterpret_cast<const float4 *>(arow + k0 + lk);
      wv = *reinterpret_cast<const float4 *>(wrow + k0 + lk);
    }
#pragma unroll
    for (int kk = 0; kk < 16; kk++) {
      float4 a0 = *reinterpret_cast<const float4 *>(&As[cur][kk][ty * 8]);
      float4 a1 = *reinterpret_cast<const float4 *>(&As[cur][kk][ty * 8 + 4]);
      float4 b  = *reinterpret_cast<const float4 *>(&Ws[cur][kk][tx * 4]);
      float am[8] = {a0.x, a0.y, a0.z, a0.w, a1.x, a1.y, a1.z, a1.w};
      float bv4[4] = {b.x, b.y, b.z, b.w};
#pragma unroll
      for (int i = 0; i < 8; i++)
#pragma unroll
        for (int j = 0; j < 4; j++)
          acc[i][j] = fmaf(am[i], bv4[j], acc[i][j]);
    }
    if (more) {
      const int nxt = cur ^ 1;
      As[nxt][lk + 0][lr] = av.x; As[nxt][lk + 1][lr] = av.y;
      As[nxt][lk + 2][lr] = av.z; As[nxt][lk + 3][lr] = av.w;
      Ws[nxt][lk + 0][lr] = wv.x; Ws[nxt][lk + 1][lr] = wv.y;
      Ws[nxt][lk + 2][lr] = wv.z; Ws[nxt][lk + 3][lr] = wv.w;
    }
    __syncthreads();
  }

#pragma unroll
  for (int i = 0; i < 8; i++) {
    int row = bm + ty * 8 + i;
    int base = row * ldc;
#pragma unroll
    for (int j = 0; j < 4; j++) {
      int col = bn + tx * 4 + j;
      C[base + col] = acc[i][j] + bias[col];
    }
  }
}

// per-row max + log(sum) from NCH chunk partials (fixed ascending chunk order).
__device__ __forceinline__ void row_stats(int row, float &m, float &l) {
  float M = g_pm[row * NCH + 0];
#pragma unroll
  for (int c = 1; c < NCH; c++) M = fmaxf(M, g_pm[row * NCH + c]);
  float s = 0.0f;
#pragma unroll
  for (int c = 0; c < NCH; c++)
    s += g_ps[row * NCH + c] * __expf(g_pm[row * NCH + c] - M);
  m = M;
  l = logf(s);
}

// ---------------- init kernel (resets barrier/state each replay) ----------------
__global__ void init_kernel() {
  int i = blockIdx.x * blockDim.x + threadIdx.x;
  if (i == 0) g_bar = 0u;
  if (i < BB) g_sampled[i] = 0;        // start token id 0
  if (i < BB * HH) g_h[i] = 0.0f;
}

// ---------------- the whole 256-step loop as one persistent kernel ----------------
__global__ void __launch_bounds__(NTHR)
actor_kernel(const float *__restrict__ embedding,
             const float *__restrict__ w_ih, const float *__restrict__ w_hh,
             const float *__restrict__ b_ih, const float *__restrict__ b_hh,
             const float *__restrict__ w_out, const float *__restrict__ b_out,
             float *__restrict__ out) {
  // GEMM double buffers dominate: 2*(16*132)*2 floats = 33792 B
  __shared__ __align__(16) float sm[2 * 16 * 132 * 2];
  const int tid = threadIdx.x;
  unsigned bar_target = 0;

  for (int t = 0; t < SS; t++) {
    // ---- Phase A: gi = emb[sampled] @ w_ih^T + b_ih ; gh = h @ w_hh^T + b_hh ----
    for (int tile = blockIdx.x; tile < 96; tile += NBLK) {
      if (tile < 48) {
        int mt = tile / 12, nt = tile % 12;
        gemm128(embedding, EE, g_sampled, EE, w_ih, EE, b_ih,
                g_gi, GG, mt * 128, nt * 128, sm);
      } else {
        int t2 = tile - 48;
        int mt = t2 / 12, nt = t2 % 12;
        gemm128(g_h, HH, nullptr, HH, w_hh, HH, b_hh,
                g_gh, GG, mt * 128, nt * 128, sm);
      }
    }
    gridbar(bar_target);

    // ---- Phase B: GRU combine (h updated in place) ----
    for (int i = blockIdx.x * NTHR + tid; i < BB * HH; i += NBLK * NTHR) {
      int b = i >> 9, j = i & 511;
      const float *gi = g_gi + b * GG;
      const float *gh = g_gh + b * GG;
      float ir = gi[j],           hr = gh[j];
      float iz = gi[j + HH],      hz = gh[j + HH];
      float in_ = gi[j + 2 * HH], hn = gh[j + 2 * HH];
      float r = 1.0f / (1.0f + expf(-(ir + hr)));
      float z = 1.0f / (1.0f + expf(-(iz + hz)));
      float n = tanhf(in_ + r * hn);
      float hp = g_h[i];
      g_h[i] = (1.0f - z) * n + z * hp;
    }
    gridbar(bar_target);

    // ---- Phase C: logits = h @ w_out^T + b_out (1000 tiles of 128x128) ----
    for (int tile = blockIdx.x; tile < 1000; tile += NBLK) {
      int mt = tile / 250, nt = tile % 250;
      gemm128(g_h, HH, nullptr, HH, w_out, HH, b_out,
              g_logits, VV, mt * 128, nt * 128, sm);
    }
    gridbar(bar_target);

    // ---- Phase D1: per (row, chunk) online max + expsum partials ----
    // Two units per block (halves in lockstep); per-unit arithmetic is the exact
    // 256-thread pattern of the validated kernel -> identical partials.
    {
      const int half = tid >> 8;        // 0 or 1
      const int lt = tid & 255;
      float *rm = sm + half * 256;
      float *rs = sm + 512 + half * 256;
      for (int u0 = blockIdx.x * 2; u0 < BB * NCH; u0 += NBLK * 2) {
        int u = u0 + half;              // always < BB*NCH (even counts)
        int row = u >> 2, c = u & (NCH - 1);
        int v0 = c * CHSZ, v1 = v0 + CHSZ;
        const float *lr = g_logits + row * VV;
        float m = -3.402823466e38f, s = 0.0f;
        for (int v = v0 + lt; v < v1; v += 256) {
          float x = lr[v];
          if (x > m) { s = s * __expf(m - x) + 1.0f; m = x; }
          else        s += __expf(x - m);
        }
        rm[lt] = m; rs[lt] = s;
        __syncthreads();
        for (int str = 128; str > 0; str >>= 1) {
          if (lt < str) {
            float m1 = rm[lt], s1 = rs[lt];
            float m2 = rm[lt + str], s2 = rs[lt + str];
            float M = fmaxf(m1, m2);
            rm[lt] = M;
            rs[lt] = s1 * __expf(m1 - M) + s2 * __expf(m2 - M);
          }
          __syncthreads();
        }
        if (lt == 0) { g_pm[u] = rm[0]; g_ps[u] = rs[0]; }
        __syncthreads();
      }
    }
    gridbar(bar_target);

    // ---- Phase D2: gumbel argmax partials per (row, chunk), two units/block ----
    {
      uint32_t kt0, kt1;
      split_key(0u, 42u, (uint32_t)t, kt0, kt1);
      uint32_t ke0, ke1, kg0, kg1;
      split_key(kt0, kt1, 0u, ke0, ke1);
      split_key(kt0, kt1, 1u, kg0, kg1);

      float tf = (float)t;
      float eps = 0.05f + 0.95f * expf((-4.0f * tf) / 10000.0f);
      const float NEG_LOGV = -10.373491181781864f;  // -float32(log(32000))

      const int half = tid >> 8;
      const int lt = tid & 255;
      float *sv = sm + half * 256;              // [2][256]
      int   *si = (int *)(sm + 512) + half * 256;

      for (int u0 = blockIdx.x * 2; u0 < BB * NCH; u0 += NBLK * 2) {
        int u = u0 + half;
        int row = u >> 2, c = u & (NCH - 1);
        int v0 = c * CHSZ, v1 = v0 + CHSZ;

        bool draw = (eps >= bits_to_uniform(rbits32(ke0, ke1, (uint32_t)row)));

        float m, l;
        row_stats(row, m, l);
        const float *lr = g_logits + row * VV;

        float bv = -3.402823466e38f;
        int bi = 0;
        for (int v = v0 + lt; v < v1; v += 256) {
          uint32_t bits = rbits32(kg0, kg1, (uint32_t)(row * VV + v));
          float g = gumbel_from_bits(bits);
          float val = draw ? (NEG_LOGV + g) : (((lr[v] - m) - l) + g);
          if (val > bv) { bv = val; bi = v; }
        }
        sv[lt] = bv; si[lt] = bi;
        __syncthreads();
        for (int str = 128; str > 0; str >>= 1) {
          if (lt < str) {
            float v2 = sv[lt + str]; int i2 = si[lt + str];
            float v1f = sv[lt];      int i1 = si[lt];
            if (v2 > v1f || (v2 == v1f && i2 < i1)) { sv[lt] = v2; si[lt] = i2; }
          }
          __syncthreads();
        }
        if (lt == 0) { g_bv[u] = sv[0]; g_bi[u] = si[0]; }
        __syncthreads();
      }
    }
    gridbar(bar_target);

    // ---- Phase E: finalize (block 0): merge chunks, write sampled + out ----
    if (blockIdx.x == 0) {
      for (int row = tid; row < BB; row += NTHR) {
        float bv = g_bv[row * NCH + 0];
        int   bi = g_bi[row * NCH + 0];
#pragma unroll
        for (int c = 1; c < NCH; c++) {
          float v2 = g_bv[row * NCH + c];
          int   i2 = g_bi[row * NCH + c];
          if (v2 > bv) { bv = v2; bi = i2; }   // ascending chunks => first-index ties kept
        }
        float m, l;
        row_stats(row, m, l);
        float lp = (g_logits[row * VV + bi] - m) - l;
        g_sampled[row] = bi;
        out[row * SS + t] = (float)bi;
        out[OUT_LP_OFF + row * SS + t] = lp;
      }
    }
    gridbar(bar_target);
  }
}

// ---------------- launch ----------------
extern "C" void kernel_launch(void *const *d_in, const int *in_sizes, int n_in,
                              void *d_out, int out_size) {
  const float *embedding = (const float *)d_in[0];  // [V,E]
  const float *w_ih      = (const float *)d_in[1];  // [3H,E]
  const float *w_hh      = (const float *)d_in[2];  // [3H,H]
  const float *b_ih      = (const float *)d_in[3];  // [3H]
  const float *b_hh      = (const float *)d_in[4];  // [3H]
  const float *w_out     = (const float *)d_in[5];  // [V,H]
  const float *b_out     = (const float *)d_in[6];  // [V]
  float *out = (float *)d_out;

  init_kernel<<<512, 512>>>();
  actor_kernel<<<NBLK, NTHR>>>(embedding, w_ih, w_hh, b_ih, b_hh,
                               w_out, b_out, out);
}

// round 10
// speedup vs baseline: 1.4279x; 1.4279x over previous
#include <cuda_runtime.h>
#include <stdint.h>
#include <math.h>

#define BB 512
#define EE 256
#define HH 512
#define GG 1536
#define VV 32000
#define SS 256
#define OUT_LP_OFF (BB*SS) // 131072

#define NBLK 148
#define NTHR 512
#define NCH 4              // v-chunks per row in D2
#define CHSZ (VV / NCH)    // 8000
#define NTILE 250          // logits n-tiles per row (32000/128)

// ---------------- scratch (device globals; no allocation allowed) ----------------
__device__ float g_h[BB * HH];
__device__ float g_gi[BB * GG];
__device__ float g_gh[BB * GG];
__device__ float g_logits[BB * VV];
__device__ float g_gum[BB * VV];        // pre-generated gumbel noise (bit-exact fp32)
__device__ int   g_sampled[BB];
__device__ float g_tpm[BB * NTILE];     // per (row, ntile) max
__device__ float g_tps[BB * NTILE];     // per (row, ntile) expsum (scaled by tile max)
__device__ float g_bv[BB * NCH];        // partial best value per (row, chunk)
__device__ int   g_bi[BB * NCH];        // partial best index
__device__ unsigned g_bar;

// ---------------- JAX threefry2x32 (exact) ----------------
__device__ __forceinline__ void tf2x32(uint32_t k0, uint32_t k1,
                                       uint32_t x0, uint32_t x1,
                                       uint32_t &o0, uint32_t &o1) {
  uint32_t k2 = k0 ^ k1 ^ 0x1BD11BDAu;
#define ROTL(x, r) (((x) << (r)) | ((x) >> (32 - (r))))
#define RND(r) { x0 += x1; x1 = ROTL(x1, r); x1 ^= x0; }
  x0 += k0; x1 += k1;
  RND(13) RND(15) RND(26) RND(6)
  x0 += k1; x1 += k2 + 1u;
  RND(17) RND(29) RND(16) RND(24)
  x0 += k2; x1 += k0 + 2u;
  RND(13) RND(15) RND(26) RND(6)
  x0 += k0; x1 += k1 + 3u;
  RND(17) RND(29) RND(16) RND(24)
  x0 += k1; x1 += k2 + 4u;
  RND(13) RND(15) RND(26) RND(6)
  x0 += k2; x1 += k0 + 5u;
#undef RND
#undef ROTL
  o0 = x0; o1 = x1;
}

// partitionable-mode: split(key,n)[i] = full output of threefry(key,(0,i))
__device__ __forceinline__ void split_key(uint32_t k0, uint32_t k1, uint32_t i,
                                          uint32_t &n0, uint32_t &n1) {
  tf2x32(k0, k1, 0u, i, n0, n1);
}

// random_bits(key,32,shape)[n] = o0 ^ o1 of threefry(key,(0,n))
__device__ __forceinline__ uint32_t rbits32(uint32_t k0, uint32_t k1, uint32_t n) {
  uint32_t o0, o1;
  tf2x32(k0, k1, 0u, n, o0, o1);
  return o0 ^ o1;
}

__device__ __forceinline__ float bits_to_uniform(uint32_t bits) {
  return __uint_as_float((bits >> 9) | 0x3f800000u) - 1.0f;
}

__device__ __forceinline__ float gumbel_from_bits(uint32_t bits) {
  float u = bits_to_uniform(bits);
  if (u == 0.0f) u = 1.17549435e-38f;   // uniform(minval=tiny): 0 -> tiny
  return -logf(-logf(u));               // accurate: argmax-critical
}

// ---------------- software grid barrier (monotonic target) ----------------
__device__ __forceinline__ void gridbar(unsigned &target) {
  target += NBLK;
  __syncthreads();
  if (threadIdx.x == 0) {
    __threadfence();
    atomicAdd(&g_bar, 1u);
    unsigned v;
    do {
      asm volatile("ld.acquire.gpu.u32 %0, [%1];" : "=r"(v) : "l"(&g_bar) : "memory");
    } while (v < target);
  }
  __syncthreads();
}

// ---------------- 128x128 fp32 TN GEMM tile (plain; used for Phase A) ----------
// Per-element: single serial fmaf chain over ascending k -> bit-identical outputs.
__device__ __forceinline__ void gemm128(
    const float *__restrict__ Abase, int aStride, const int *gather,
    int Krun, const float *__restrict__ W, int wStride,
    const float *__restrict__ bias, float *__restrict__ C, int ldc,
    int bm, int bn, float *sm) {
  float (*As)[16][132] = reinterpret_cast<float (*)[16][132]>(sm);
  float (*Ws)[16][132] = reinterpret_cast<float (*)[16][132]>(sm + 2 * 16 * 132);
  const int tid = threadIdx.x;
  const int tx = tid & 31;
  const int ty = tid >> 5;
  const int lr = tid >> 2;
  const int lk = (tid & 3) * 4;

  const int arowi = gather ? gather[bm + lr] : (bm + lr);
  const float *arow = Abase + (size_t)arowi * aStride;
  const float *wrow = W + (size_t)(bn + lr) * wStride;

  float acc[8][4];
#pragma unroll
  for (int i = 0; i < 8; i++)
#pragma unroll
    for (int j = 0; j < 4; j++) acc[i][j] = 0.0f;

  {
    float4 av = *reinterpret_cast<const float4 *>(arow + lk);
    float4 wv = *reinterpret_cast<const float4 *>(wrow + lk);
    As[0][lk + 0][lr] = av.x; As[0][lk + 1][lr] = av.y;
    As[0][lk + 2][lr] = av.z; As[0][lk + 3][lr] = av.w;
    Ws[0][lk + 0][lr] = wv.x; Ws[0][lk + 1][lr] = wv.y;
    Ws[0][lk + 2][lr] = wv.z; Ws[0][lk + 3][lr] = wv.w;
  }
  __syncthreads();

  const int nk = Krun >> 4;
#pragma unroll 1
  for (int kt = 0; kt < nk; kt++) {
    const int cur = kt & 1;
    float4 av, wv;
    const bool more = (kt + 1 < nk);
    if (more) {
      int k0 = (kt + 1) << 4;
      av = *reinterpret_cast<const float4 *>(arow + k0 + lk);
      wv = *reinterpret_cast<const float4 *>(wrow + k0 + lk);
    }
#pragma unroll
    for (int kk = 0; kk < 16; kk++) {
      float4 a0 = *reinterpret_cast<const float4 *>(&As[cur][kk][ty * 8]);
      float4 a1 = *reinterpret_cast<const float4 *>(&As[cur][kk][ty * 8 + 4]);
      float4 b  = *reinterpret_cast<const float4 *>(&Ws[cur][kk][tx * 4]);
      float am[8] = {a0.x, a0.y, a0.z, a0.w, a1.x, a1.y, a1.z, a1.w};
      float bv4[4] = {b.x, b.y, b.z, b.w};
#pragma unroll
      for (int i = 0; i < 8; i++)
#pragma unroll
        for (int j = 0; j < 4; j++)
          acc[i][j] = fmaf(am[i], bv4[j], acc[i][j]);
    }
    if (more) {
      const int nxt = cur ^ 1;
      As[nxt][lk + 0][lr] = av.x; As[nxt][lk + 1][lr] = av.y;
      As[nxt][lk + 2][lr] = av.z; As[nxt][lk + 3][lr] = av.w;
      Ws[nxt][lk + 0][lr] = wv.x; Ws[nxt][lk + 1][lr] = wv.y;
      Ws[nxt][lk + 2][lr] = wv.z; Ws[nxt][lk + 3][lr] = wv.w;
    }
    __syncthreads();
  }

#pragma unroll
  for (int i = 0; i < 8; i++) {
    int row = bm + ty * 8 + i;
    int base = row * ldc;
#pragma unroll
    for (int j = 0; j < 4; j++) {
      int col = bn + tx * 4 + j;
      C[base + col] = acc[i][j] + bias[col];
    }
  }
}

// ------- Phase C tile: logits GEMM + fused gumbel generation + row-stat partials ----
// Identical FFMA chain to gemm128 (bit-identical logits). Per k-tile iteration each
// thread additionally generates one gumbel element (ALU pipe; FMA pipe has idle
// issue slots at rt=2). Epilogue computes per-tile per-row max/expsum partials.
__device__ __forceinline__ void gemm_logits(
    const float *__restrict__ h, const float *__restrict__ W,
    const float *__restrict__ bias, int bm, int nt,
    uint32_t kg0, uint32_t kg1, int tileIdx, float *sm) {
  float (*As)[16][132] = reinterpret_cast<float (*)[16][132]>(sm);
  float (*Ws)[16][132] = reinterpret_cast<float (*)[16][132]>(sm + 2 * 16 * 132);
  const int tid = threadIdx.x;
  const int tx = tid & 31;
  const int ty = tid >> 5;
  const int lr = tid >> 2;
  const int lk = (tid & 3) * 4;
  const int bn = nt * 128;

  const float *arow = h + (size_t)(bm + lr) * HH;
  const float *wrow = W + (size_t)(bn + lr) * HH;

  float acc[8][4];
#pragma unroll
  for (int i = 0; i < 8; i++)
#pragma unroll
    for (int j = 0; j < 4; j++) acc[i][j] = 0.0f;

  {
    float4 av = *reinterpret_cast<const float4 *>(arow + lk);
    float4 wv = *reinterpret_cast<const float4 *>(wrow + lk);
    As[0][lk + 0][lr] = av.x; As[0][lk + 1][lr] = av.y;
    As[0][lk + 2][lr] = av.z; As[0][lk + 3][lr] = av.w;
    Ws[0][lk + 0][lr] = wv.x; Ws[0][lk + 1][lr] = wv.y;
    Ws[0][lk + 2][lr] = wv.z; Ws[0][lk + 3][lr] = wv.w;
  }
  __syncthreads();

  const uint32_t ebase = (uint32_t)tileIdx * 16384u + (uint32_t)tid;
  const int nk = HH >> 4;  // 32 -> 32*512 = 16384 gumbels per tile
#pragma unroll 1
  for (int kt = 0; kt < nk; kt++) {
    const int cur = kt & 1;
    float4 av, wv;
    const bool more = (kt + 1 < nk);
    if (more) {
      int k0 = (kt + 1) << 4;
      av = *reinterpret_cast<const float4 *>(arow + k0 + lk);
      wv = *reinterpret_cast<const float4 *>(wrow + k0 + lk);
    }
    // fused gumbel generation (ALU/MUFU; fills FMA-idle issue slots + LDG latency)
    {
      uint32_t e = ebase + (uint32_t)(kt << 9);
      g_gum[e] = gumbel_from_bits(rbits32(kg0, kg1, e));
    }
#pragma unroll
    for (int kk = 0; kk < 16; kk++) {
      float4 a0 = *reinterpret_cast<const float4 *>(&As[cur][kk][ty * 8]);
      float4 a1 = *reinterpret_cast<const float4 *>(&As[cur][kk][ty * 8 + 4]);
      float4 b  = *reinterpret_cast<const float4 *>(&Ws[cur][kk][tx * 4]);
      float am[8] = {a0.x, a0.y, a0.z, a0.w, a1.x, a1.y, a1.z, a1.w};
      float bv4[4] = {b.x, b.y, b.z, b.w};
#pragma unroll
      for (int i = 0; i < 8; i++)
#pragma unroll
        for (int j = 0; j < 4; j++)
          acc[i][j] = fmaf(am[i], bv4[j], acc[i][j]);
    }
    if (more) {
      const int nxt = cur ^ 1;
      As[nxt][lk + 0][lr] = av.x; As[nxt][lk + 1][lr] = av.y;
      As[nxt][lk + 2][lr] = av.z; As[nxt][lk + 3][lr] = av.w;
      Ws[nxt][lk + 0][lr] = wv.x; Ws[nxt][lk + 1][lr] = wv.y;
      Ws[nxt][lk + 2][lr] = wv.z; Ws[nxt][lk + 3][lr] = wv.w;
    }
    __syncthreads();
  }

  // epilogue: bias add + store logits + per-tile row stats (warp = one row set)
#pragma unroll
  for (int i = 0; i < 8; i++) {
    int row = bm + ty * 8 + i;
    int base = row * VV;
    float v0 = acc[i][0] + bias[bn + tx * 4 + 0];
    float v1 = acc[i][1] + bias[bn + tx * 4 + 1];
    float v2 = acc[i][2] + bias[bn + tx * 4 + 2];
    float v3 = acc[i][3] + bias[bn + tx * 4 + 3];
    g_logits[base + bn + tx * 4 + 0] = v0;
    g_logits[base + bn + tx * 4 + 1] = v1;
    g_logits[base + bn + tx * 4 + 2] = v2;
    g_logits[base + bn + tx * 4 + 3] = v3;
    // warp-wide row max over this tile's 128 cols
    float mloc = fmaxf(fmaxf(v0, v1), fmaxf(v2, v3));
#pragma unroll
    for (int off = 16; off > 0; off >>= 1)
      mloc = fmaxf(mloc, __shfl_xor_sync(0xffffffffu, mloc, off));
    float sloc = __expf(v0 - mloc) + __expf(v1 - mloc) +
                 __expf(v2 - mloc) + __expf(v3 - mloc);
#pragma unroll
    for (int off = 16; off > 0; off >>= 1)
      sloc += __shfl_xor_sync(0xffffffffu, sloc, off);
    if (tx == 0) {
      g_tpm[row * NTILE + nt] = mloc;
      g_tps[row * NTILE + nt] = sloc;
    }
  }
}

// serial per-row stats from the NTILE partials (fixed ascending order; used in E)
__device__ __forceinline__ void row_stats_serial(int row, float &m, float &l) {
  const float *pm = g_tpm + row * NTILE;
  const float *ps = g_tps + row * NTILE;
  float M = pm[0];
  for (int c = 1; c < NTILE; c++) M = fmaxf(M, pm[c]);
  float s = 0.0f;
  for (int c = 0; c < NTILE; c++) s += ps[c] * __expf(pm[c] - M);
  m = M;
  l = logf(s);
}

// ---------------- init kernel (resets barrier/state each replay) ----------------
__global__ void init_kernel() {
  int i = blockIdx.x * blockDim.x + threadIdx.x;
  if (i == 0) g_bar = 0u;
  if (i < BB) g_sampled[i] = 0;        // start token id 0
  if (i < BB * HH) g_h[i] = 0.0f;
}

// ---------------- the whole 256-step loop as one persistent kernel ----------------
__global__ void __launch_bounds__(NTHR)
actor_kernel(const float *__restrict__ embedding,
             const float *__restrict__ w_ih, const float *__restrict__ w_hh,
             const float *__restrict__ b_ih, const float *__restrict__ b_hh,
             const float *__restrict__ w_out, const float *__restrict__ b_out,
             float *__restrict__ out) {
  __shared__ __align__(16) float sm[2 * 16 * 132 * 2];  // 33.8 KB, reused per phase
  const int tid = threadIdx.x;
  unsigned bar_target = 0;

  for (int t = 0; t < SS; t++) {
    // per-step keys (partitionable scheme; validated bit-exact)
    uint32_t kt0, kt1, ke0, ke1, kg0, kg1;
    split_key(0u, 42u, (uint32_t)t, kt0, kt1);
    split_key(kt0, kt1, 0u, ke0, ke1);
    split_key(kt0, kt1, 1u, kg0, kg1);
    const float eps = 0.05f + 0.95f * expf((-4.0f * (float)t) / 10000.0f);
    const float NEG_LOGV = -10.373491181781864f;  // -float32(log(32000))

    // ---- Phase A: gi = emb[sampled] @ w_ih^T + b_ih ; gh = h @ w_hh^T + b_hh ----
    for (int tile = blockIdx.x; tile < 96; tile += NBLK) {
      if (tile < 48) {
        int mt = tile / 12, nt = tile % 12;
        gemm128(embedding, EE, g_sampled, EE, w_ih, EE, b_ih,
                g_gi, GG, mt * 128, nt * 128, sm);
      } else {
        int t2 = tile - 48;
        int mt = t2 / 12, nt = t2 % 12;
        gemm128(g_h, HH, nullptr, HH, w_hh, HH, b_hh,
                g_gh, GG, mt * 128, nt * 128, sm);
      }
    }
    gridbar(bar_target);

    // ---- Phase B: GRU combine (h updated in place) ----
    for (int i = blockIdx.x * NTHR + tid; i < BB * HH; i += NBLK * NTHR) {
      int b = i >> 9, j = i & 511;
      const float *gi = g_gi + b * GG;
      const float *gh = g_gh + b * GG;
      float ir = gi[j],           hr = gh[j];
      float iz = gi[j + HH],      hz = gh[j + HH];
      float in_ = gi[j + 2 * HH], hn = gh[j + 2 * HH];
      float r = 1.0f / (1.0f + expf(-(ir + hr)));
      float z = 1.0f / (1.0f + expf(-(iz + hz)));
      float n = tanhf(in_ + r * hn);
      float hp = g_h[i];
      g_h[i] = (1.0f - z) * n + z * hp;
    }
    gridbar(bar_target);

    // ---- Phase C: logits GEMM + fused gumbel gen + row-stat partials ----
    for (int tile = blockIdx.x; tile < 1000; tile += NBLK) {
      int mt = tile / NTILE, nt = tile % NTILE;
      gemm_logits(g_h, w_out, b_out, mt * 128, nt, kg0, kg1, tile, sm);
    }
    gridbar(bar_target);

    // ---- Phase D2: argmax scan per (row, chunk); two units per block ----
    {
      const int half = tid >> 8;
      const int lt = tid & 255;
      float *sv = sm + half * 256;                     // value scratch
      int   *si = (int *)(sm + 512) + half * 256;      // index scratch
      float *rr = sm + 1024 + half * 256;              // stats scratch

      for (int u0 = blockIdx.x * 2; u0 < BB * NCH; u0 += NBLK * 2) {
        int u = u0 + half;
        int row = u >> 2, c = u & (NCH - 1);
        int v0 = c * CHSZ, v1 = v0 + CHSZ;

        bool draw = (eps >= bits_to_uniform(rbits32(ke0, ke1, (uint32_t)row)));

        // row stats from NTILE partials (cooperative tree reduce)
        float mloc = (lt < NTILE) ? g_tpm[row * NTILE + lt] : -3.402823466e38f;
        rr[lt] = mloc;
        __syncthreads();
        for (int str = 128; str > 0; str >>= 1) {
          if (lt < str) rr[lt] = fmaxf(rr[lt], rr[lt + str]);
          __syncthreads();
        }
        float M = rr[0];
        __syncthreads();
        float con = (lt < NTILE)
            ? g_tps[row * NTILE + lt] * __expf(g_tpm[row * NTILE + lt] - M) : 0.0f;
        rr[lt] = con;
        __syncthreads();
        for (int str = 128; str > 0; str >>= 1) {
          if (lt < str) rr[lt] += rr[lt + str];
          __syncthreads();
        }
        float L = logf(rr[0]);
        __syncthreads();

        const float *lr = g_logits + row * VV;
        const float *gr = g_gum + row * VV;

        float bv = -3.402823466e38f;
        int bi = 0;
        for (int v = v0 + lt; v < v1; v += 256) {
          float g = gr[v];
          float val = draw ? (NEG_LOGV + g) : (((lr[v] - M) - L) + g);
          if (val > bv) { bv = val; bi = v; }
        }
        sv[lt] = bv; si[lt] = bi;
        __syncthreads();
        for (int str = 128; str > 0; str >>= 1) {
          if (lt < str) {
            float v2 = sv[lt + str]; int i2 = si[lt + str];
            float v1f = sv[lt];      int i1 = si[lt];
            if (v2 > v1f || (v2 == v1f && i2 < i1)) { sv[lt] = v2; si[lt] = i2; }
          }
          __syncthreads();
        }
        if (lt == 0) { g_bv[u] = sv[0]; g_bi[u] = si[0]; }
        __syncthreads();
      }
    }
    gridbar(bar_target);

    // ---- Phase E: finalize (block 0): merge chunks, write sampled + out ----
    if (blockIdx.x == 0) {
      for (int row = tid; row < BB; row += NTHR) {
        float bv = g_bv[row * NCH + 0];
        int   bi = g_bi[row * NCH + 0];
#pragma unroll
        for (int c = 1; c < NCH; c++) {
          float v2 = g_bv[row * NCH + c];
          int   i2 = g_bi[row * NCH + c];
          if (v2 > bv) { bv = v2; bi = i2; }   // ascending chunks => first-index ties kept
        }
        float m, l;
        row_stats_serial(row, m, l);
        float lp = (g_logits[row * VV + bi] - m) - l;
        g_sampled[row] = bi;
        out[row * SS + t] = (float)bi;
        out[OUT_LP_OFF + row * SS + t] = lp;
      }
    }
    gridbar(bar_target);
  }
}

// ---------------- launch ----------------
extern "C" void kernel_launch(void *const *d_in, const int *in_sizes, int n_in,
                              void *d_out, int out_size) {
  const float *embedding = (const float *)d_in[0];  // [V,E]
  const float *w_ih      = (const float *)d_in[1];  // [3H,E]
  const float *w_hh      = (const float *)d_in[2];  // [3H,H]
  const float *b_ih      = (const float *)d_in[3];  // [3H]
  const float *b_hh      = (const float *)d_in[4];  // [3H]
  const float *w_out     = (const float *)d_in[5];  // [V,H]
  const float *b_out     = (const float *)d_in[6];  // [V]
  float *out = (float *)d_out;

  init_kernel<<<512, 512>>>();
  actor_kernel<<<NBLK, NTHR>>>(embedding, w_ih, w_hh, b_ih, b_hh,
                               w_out, b_out, out);
}

// round 13
// speedup vs baseline: 1.7960x; 1.2577x over previous
#include <cuda_runtime.h>
#include <stdint.h>
#include <math.h>

#define BB 512
#define EE 256
#define HH 512
#define GG 1536
#define VV 32000
#define SS 256
#define OUT_LP_OFF (BB*SS) // 131072

#define NBLK 148
#define NTHR 512
#define NTILE 250          // logits n-tiles per row (32000/128)

// ---------------- scratch (device globals; no allocation allowed) ----------------
__device__ float g_h[BB * HH];
__device__ float g_gi[BB * GG];
__device__ float g_gh[BB * GG];
__device__ float g_logits[BB * VV];
__device__ float g_gum[BB * VV];        // gumbel noise (bit-exact fp32)
__device__ int   g_sampled[BB];
__device__ float g_tpm[BB * NTILE];     // per (row, ntile) max
__device__ float g_tps[BB * NTILE];     // per (row, ntile) expsum (scaled by tile max)
__device__ unsigned g_bar;

// ---------------- packed fp32x2 FMA (sm_103a; 2 independent IEEE fmaf) ----------
#define FMA2(acc, a, b) \
  asm("fma.rn.f32x2 %0, %1, %2, %0;" : "+l"(acc) : "l"(a), "l"(b))
#define PACK_DUP(d, f) \
  asm("mov.b64 %0, {%1, %1};" : "=l"(d) : "f"(f))

__device__ __forceinline__ float lo32(unsigned long long v) {
  return __uint_as_float((unsigned)(v & 0xffffffffull));
}
__device__ __forceinline__ float hi32(unsigned long long v) {
  return __uint_as_float((unsigned)(v >> 32));
}

// ---------------- JAX threefry2x32 (exact) ----------------
__device__ __forceinline__ void tf2x32(uint32_t k0, uint32_t k1,
                                       uint32_t x0, uint32_t x1,
                                       uint32_t &o0, uint32_t &o1) {
  uint32_t k2 = k0 ^ k1 ^ 0x1BD11BDAu;
#define ROTL(x, r) (((x) << (r)) | ((x) >> (32 - (r))))
#define RND(r) { x0 += x1; x1 = ROTL(x1, r); x1 ^= x0; }
  x0 += k0; x1 += k1;
  RND(13) RND(15) RND(26) RND(6)
  x0 += k1; x1 += k2 + 1u;
  RND(17) RND(29) RND(16) RND(24)
  x0 += k2; x1 += k0 + 2u;
  RND(13) RND(15) RND(26) RND(6)
  x0 += k0; x1 += k1 + 3u;
  RND(17) RND(29) RND(16) RND(24)
  x0 += k1; x1 += k2 + 4u;
  RND(13) RND(15) RND(26) RND(6)
  x0 += k2; x1 += k0 + 5u;
#undef RND
#undef ROTL
  o0 = x0; o1 = x1;
}

// partitionable-mode: split(key,n)[i] = full output of threefry(key,(0,i))
__device__ __forceinline__ void split_key(uint32_t k0, uint32_t k1, uint32_t i,
                                          uint32_t &n0, uint32_t &n1) {
  tf2x32(k0, k1, 0u, i, n0, n1);
}

// random_bits(key,32,shape)[n] = o0 ^ o1 of threefry(key,(0,n))
__device__ __forceinline__ uint32_t rbits32(uint32_t k0, uint32_t k1, uint32_t n) {
  uint32_t o0, o1;
  tf2x32(k0, k1, 0u, n, o0, o1);
  return o0 ^ o1;
}

__device__ __forceinline__ float bits_to_uniform(uint32_t bits) {
  return __uint_as_float((bits >> 9) | 0x3f800000u) - 1.0f;
}

__device__ __forceinline__ float gumbel_from_bits(uint32_t bits) {
  float u = bits_to_uniform(bits);
  if (u == 0.0f) u = 1.17549435e-38f;   // uniform(minval=tiny): 0 -> tiny
  return -logf(-logf(u));               // accurate: argmax-critical
}

// ---------------- software grid barrier (monotonic target) ----------------
__device__ __forceinline__ void gridbar(unsigned &target) {
  target += NBLK;
  __syncthreads();
  if (threadIdx.x == 0) {
    __threadfence();
    atomicAdd(&g_bar, 1u);
    unsigned v;
    do {
      asm volatile("ld.acquire.gpu.u32 %0, [%1];" : "=r"(v) : "l"(&g_bar) : "memory");
    } while (v < target);
  }
  __syncthreads();
}

// ---------------- 128x128 fp32 TN GEMM tile, f32x2 packed-M, 512 threads -------
// Each u64 accumulator lane is an independent serial fmaf chain over ascending k
// -> outputs bit-identical to the validated scalar kernel.
__device__ __forceinline__ void gemm128(
    const float *__restrict__ Abase, int aStride, const int *gather,
    int Krun, const float *__restrict__ W, int wStride,
    const float *__restrict__ bias, float *__restrict__ C, int ldc,
    int bm, int bn, float *sm) {
  float (*As)[16][132] = reinterpret_cast<float (*)[16][132]>(sm);
  float (*Ws)[16][132] = reinterpret_cast<float (*)[16][132]>(sm + 2 * 16 * 132);
  const int tid = threadIdx.x;
  const int tx = tid & 31;
  const int ty = tid >> 5;
  const int lr = tid >> 2;
  const int lk = (tid & 3) * 4;

  const int arowi = gather ? gather[bm + lr] : (bm + lr);
  const float *arow = Abase + (size_t)arowi * aStride;
  const float *wrow = W + (size_t)(bn + lr) * wStride;

  unsigned long long acc2[4][4];   // [row-pair][col]; lanes (2ip, 2ip+1)
#pragma unroll
  for (int ip = 0; ip < 4; ip++)
#pragma unroll
    for (int j = 0; j < 4; j++) acc2[ip][j] = 0ull;

  {
    float4 av = *reinterpret_cast<const float4 *>(arow + lk);
    float4 wv = *reinterpret_cast<const float4 *>(wrow + lk);
    As[0][lk + 0][lr] = av.x; As[0][lk + 1][lr] = av.y;
    As[0][lk + 2][lr] = av.z; As[0][lk + 3][lr] = av.w;
    Ws[0][lk + 0][lr] = wv.x; Ws[0][lk + 1][lr] = wv.y;
    Ws[0][lk + 2][lr] = wv.z; Ws[0][lk + 3][lr] = wv.w;
  }
  __syncthreads();

  const int nk = Krun >> 4;
#pragma unroll 1
  for (int kt = 0; kt < nk; kt++) {
    const int cur = kt & 1;
    float4 av, wv;
    const bool more = (kt + 1 < nk);
    if (more) {
      int k0 = (kt + 1) << 4;
      av = *reinterpret_cast<const float4 *>(arow + k0 + lk);
      wv = *reinterpret_cast<const float4 *>(wrow + k0 + lk);
    }
#pragma unroll
    for (int kk = 0; kk < 16; kk++) {
      const ulonglong2 *pa =
          reinterpret_cast<const ulonglong2 *>(&As[cur][kk][ty * 8]);
      ulonglong2 aA = pa[0];        // rows (0,1),(2,3)
      ulonglong2 aB = pa[1];        // rows (4,5),(6,7)
      float4 b = *reinterpret_cast<const float4 *>(&Ws[cur][kk][tx * 4]);
      unsigned long long ap[4] = {aA.x, aA.y, aB.x, aB.y};
      unsigned long long bd[4];
      PACK_DUP(bd[0], b.x); PACK_DUP(bd[1], b.y);
      PACK_DUP(bd[2], b.z); PACK_DUP(bd[3], b.w);
#pragma unroll
      for (int ip = 0; ip < 4; ip++)
#pragma unroll
        for (int j = 0; j < 4; j++)
          FMA2(acc2[ip][j], ap[ip], bd[j]);
    }
    if (more) {
      const int nxt = cur ^ 1;
      As[nxt][lk + 0][lr] = av.x; As[nxt][lk + 1][lr] = av.y;
      As[nxt][lk + 2][lr] = av.z; As[nxt][lk + 3][lr] = av.w;
      Ws[nxt][lk + 0][lr] = wv.x; Ws[nxt][lk + 1][lr] = wv.y;
      Ws[nxt][lk + 2][lr] = wv.z; Ws[nxt][lk + 3][lr] = wv.w;
    }
    __syncthreads();
  }

#pragma unroll
  for (int ip = 0; ip < 4; ip++)
#pragma unroll
    for (int half = 0; half < 2; half++) {
      int row = bm + ty * 8 + 2 * ip + half;
      int base = row * ldc;
#pragma unroll
      for (int j = 0; j < 4; j++) {
        int col = bn + tx * 4 + j;
        float v = half ? hi32(acc2[ip][j]) : lo32(acc2[ip][j]);
        C[base + col] = v + bias[col];
      }
    }
}

// ------- Phase C tile: logits GEMM (f32x2) + fused gumbel gen + row-stat partials
__device__ __forceinline__ void gemm_logits(
    const float *__restrict__ h, const float *__restrict__ W,
    const float *__restrict__ bias, int bm, int nt,
    uint32_t kg0, uint32_t kg1, int tileIdx, float *sm) {
  float (*As)[16][132] = reinterpret_cast<float (*)[16][132]>(sm);
  float (*Ws)[16][132] = reinterpret_cast<float (*)[16][132]>(sm + 2 * 16 * 132);
  const int tid = threadIdx.x;
  const int tx = tid & 31;
  const int ty = tid >> 5;
  const int lr = tid >> 2;
  const int lk = (tid & 3) * 4;
  const int bn = nt * 128;

  const float *arow = h + (size_t)(bm + lr) * HH;
  const float *wrow = W + (size_t)(bn + lr) * HH;

  unsigned long long acc2[4][4];
#pragma unroll
  for (int ip = 0; ip < 4; ip++)
#pragma unroll
    for (int j = 0; j < 4; j++) acc2[ip][j] = 0ull;

  {
    float4 av = *reinterpret_cast<const float4 *>(arow + lk);
    float4 wv = *reinterpret_cast<const float4 *>(wrow + lk);
    As[0][lk + 0][lr] = av.x; As[0][lk + 1][lr] = av.y;
    As[0][lk + 2][lr] = av.z; As[0][lk + 3][lr] = av.w;
    Ws[0][lk + 0][lr] = wv.x; Ws[0][lk + 1][lr] = wv.y;
    Ws[0][lk + 2][lr] = wv.z; Ws[0][lk + 3][lr] = wv.w;
  }
  __syncthreads();

  const uint32_t ebase = (uint32_t)tileIdx * 16384u + (uint32_t)tid;
  const int nk = HH >> 4;  // 32 -> 32*512 = 16384 gumbels per tile
#pragma unroll 1
  for (int kt = 0; kt < nk; kt++) {
    const int cur = kt & 1;
    float4 av, wv;
    const bool more = (kt + 1 < nk);
    if (more) {
      int k0 = (kt + 1) << 4;
      av = *reinterpret_cast<const float4 *>(arow + k0 + lk);
      wv = *reinterpret_cast<const float4 *>(wrow + k0 + lk);
    }
    // fused gumbel generation (ALU/MUFU pipes; FMA pipe stays saturated)
    {
      uint32_t e = ebase + (uint32_t)(kt << 9);
      g_gum[e] = gumbel_from_bits(rbits32(kg0, kg1, e));
    }
#pragma unroll
    for (int kk = 0; kk < 16; kk++) {
      const ulonglong2 *pa =
          reinterpret_cast<const ulonglong2 *>(&As[cur][kk][ty * 8]);
      ulonglong2 aA = pa[0];
      ulonglong2 aB = pa[1];
      float4 b = *reinterpret_cast<const float4 *>(&Ws[cur][kk][tx * 4]);
      unsigned long long ap[4] = {aA.x, aA.y, aB.x, aB.y};
      unsigned long long bd[4];
      PACK_DUP(bd[0], b.x); PACK_DUP(bd[1], b.y);
      PACK_DUP(bd[2], b.z); PACK_DUP(bd[3], b.w);
#pragma unroll
      for (int ip = 0; ip < 4; ip++)
#pragma unroll
        for (int j = 0; j < 4; j++)
          FMA2(acc2[ip][j], ap[ip], bd[j]);
    }
    if (more) {
      const int nxt = cur ^ 1;
      As[nxt][lk + 0][lr] = av.x; As[nxt][lk + 1][lr] = av.y;
      As[nxt][lk + 2][lr] = av.z; As[nxt][lk + 3][lr] = av.w;
      Ws[nxt][lk + 0][lr] = wv.x; Ws[nxt][lk + 1][lr] = wv.y;
      Ws[nxt][lk + 2][lr] = wv.z; Ws[nxt][lk + 3][lr] = wv.w;
    }
    __syncthreads();
  }

  // epilogue: bias add + store logits + per-tile row stats (warp = one row)
#pragma unroll
  for (int ip = 0; ip < 4; ip++)
#pragma unroll
    for (int half = 0; half < 2; half++) {
      int row = bm + ty * 8 + 2 * ip + half;
      int base = row * VV;
      float v0 = (half ? hi32(acc2[ip][0]) : lo32(acc2[ip][0])) + bias[bn + tx * 4 + 0];
      float v1 = (half ? hi32(acc2[ip][1]) : lo32(acc2[ip][1])) + bias[bn + tx * 4 + 1];
      float v2 = (half ? hi32(acc2[ip][2]) : lo32(acc2[ip][2])) + bias[bn + tx * 4 + 2];
      float v3 = (half ? hi32(acc2[ip][3]) : lo32(acc2[ip][3])) + bias[bn + tx * 4 + 3];
      g_logits[base + bn + tx * 4 + 0] = v0;
      g_logits[base + bn + tx * 4 + 1] = v1;
      g_logits[base + bn + tx * 4 + 2] = v2;
      g_logits[base + bn + tx * 4 + 3] = v3;
      float mloc = fmaxf(fmaxf(v0, v1), fmaxf(v2, v3));
#pragma unroll
      for (int off = 16; off > 0; off >>= 1)
        mloc = fmaxf(mloc, __shfl_xor_sync(0xffffffffu, mloc, off));
      float sloc = __expf(v0 - mloc) + __expf(v1 - mloc) +
                   __expf(v2 - mloc) + __expf(v3 - mloc);
#pragma unroll
      for (int off = 16; off > 0; off >>= 1)
        sloc += __shfl_xor_sync(0xffffffffu, sloc, off);
      if (tx == 0) {
        g_tpm[row * NTILE + nt] = mloc;
        g_tps[row * NTILE + nt] = sloc;
      }
    }
}

// ---------------- init kernel (resets barrier/state each replay) ----------------
__global__ void init_kernel() {
  int i = blockIdx.x * blockDim.x + threadIdx.x;
  if (i == 0) g_bar = 0u;
  if (i < BB) g_sampled[i] = 0;        // start token id 0
  if (i < BB * HH) g_h[i] = 0.0f;
}

// ---------------- the whole 256-step loop as one persistent kernel ----------------
__global__ void __launch_bounds__(NTHR)
actor_kernel(const float *__restrict__ embedding,
             const float *__restrict__ w_ih, const float *__restrict__ w_hh,
             const float *__restrict__ b_ih, const float *__restrict__ b_hh,
             const float *__restrict__ w_out, const float *__restrict__ b_out,
             float *__restrict__ out) {
  __shared__ __align__(16) float sm[2 * 16 * 132 * 2];  // 33.8 KB, reused per phase
  const int tid = threadIdx.x;
  unsigned bar_target = 0;

  for (int t = 0; t < SS; t++) {
    // per-step keys (partitionable scheme; validated bit-exact)
    uint32_t kt0, kt1, ke0, ke1, kg0, kg1;
    split_key(0u, 42u, (uint32_t)t, kt0, kt1);
    split_key(kt0, kt1, 0u, ke0, ke1);
    split_key(kt0, kt1, 1u, kg0, kg1);
    const float eps = 0.05f + 0.95f * expf((-4.0f * (float)t) / 10000.0f);
    const float NEG_LOGV = -10.373491181781864f;  // -float32(log(32000))

    // ---- Phase A: gi = emb[sampled] @ w_ih^T + b_ih ; gh = h @ w_hh^T + b_hh ----
    for (int tile = blockIdx.x; tile < 96; tile += NBLK) {
      if (tile < 48) {
        int mt = tile / 12, nt = tile % 12;
        gemm128(embedding, EE, g_sampled, EE, w_ih, EE, b_ih,
                g_gi, GG, mt * 128, nt * 128, sm);
      } else {
        int t2 = tile - 48;
        int mt = t2 / 12, nt = t2 % 12;
        gemm128(g_h, HH, nullptr, HH, w_hh, HH, b_hh,
                g_gh, GG, mt * 128, nt * 128, sm);
      }
    }
    gridbar(bar_target);

    // ---- Phase B: GRU combine (h updated in place) ----
    for (int i = blockIdx.x * NTHR + tid; i < BB * HH; i += NBLK * NTHR) {
      int b = i >> 9, j = i & 511;
      const float *gi = g_gi + b * GG;
      const float *gh = g_gh + b * GG;
      float ir = gi[j],           hr = gh[j];
      float iz = gi[j + HH],      hz = gh[j + HH];
      float in_ = gi[j + 2 * HH], hn = gh[j + 2 * HH];
      float r = 1.0f / (1.0f + expf(-(ir + hr)));
      float z = 1.0f / (1.0f + expf(-(iz + hz)));
      float n = tanhf(in_ + r * hn);
      float hp = g_h[i];
      g_h[i] = (1.0f - z) * n + z * hp;
    }
    gridbar(bar_target);

    // ---- Phase C: logits GEMM (f32x2) + fused gumbel gen + row-stat partials ----
    for (int tile = blockIdx.x; tile < 1000; tile += NBLK) {
      int mt = tile / NTILE, nt = tile % NTILE;
      gemm_logits(g_h, w_out, b_out, mt * 128, nt, kg0, kg1, tile, sm);
    }
    gridbar(bar_target);

    // ---- Phase D: per-row stats + gumbel argmax + finalize (one row per block) ----
    {
      float *sv = sm;                       // [512] values
      int   *si = (int *)(sm + 512);        // [512] indices
      float *rr = sm + 1024;                // [512] stats scratch

      for (int row = blockIdx.x; row < BB; row += NBLK) {
        bool draw = (eps >= bits_to_uniform(rbits32(ke0, ke1, (uint32_t)row)));

        // row stats from NTILE partials (cooperative tree reduce)
        rr[tid] = (tid < NTILE) ? g_tpm[row * NTILE + tid] : -3.402823466e38f;
        __syncthreads();
        for (int str = 256; str > 0; str >>= 1) {
          if (tid < str) rr[tid] = fmaxf(rr[tid], rr[tid + str]);
          __syncthreads();
        }
        float M = rr[0];
        __syncthreads();
        rr[tid] = (tid < NTILE)
            ? g_tps[row * NTILE + tid] * __expf(g_tpm[row * NTILE + tid] - M) : 0.0f;
        __syncthreads();
        for (int str = 256; str > 0; str >>= 1) {
          if (tid < str) rr[tid] += rr[tid + str];
          __syncthreads();
        }
        float L = logf(rr[0]);
        __syncthreads();

        const float4 *lr4 = reinterpret_cast<const float4 *>(g_logits + row * VV);
        const float4 *gr4 = reinterpret_cast<const float4 *>(g_gum + row * VV);

        float bv = -3.402823466e38f;
        int bi = 0;
        for (int q = tid; q < VV / 4; q += NTHR) {
          float4 l4 = lr4[q];
          float4 g4 = gr4[q];
          int v = q * 4;
          float c0 = draw ? (NEG_LOGV + g4.x) : (((l4.x - M) - L) + g4.x);
          float c1 = draw ? (NEG_LOGV + g4.y) : (((l4.y - M) - L) + g4.y);
          float c2 = draw ? (NEG_LOGV + g4.z) : (((l4.z - M) - L) + g4.z);
          float c3 = draw ? (NEG_LOGV + g4.w) : (((l4.w - M) - L) + g4.w);
          if (c0 > bv) { bv = c0; bi = v; }
          if (c1 > bv) { bv = c1; bi = v + 1; }
          if (c2 > bv) { bv = c2; bi = v + 2; }
          if (c3 > bv) { bv = c3; bi = v + 3; }
        }
        sv[tid] = bv; si[tid] = bi;
        __syncthreads();
        for (int str = 256; str > 0; str >>= 1) {
          if (tid < str) {
            float v2 = sv[tid + str]; int i2 = si[tid + str];
            float v1f = sv[tid];      int i1 = si[tid];
            if (v2 > v1f || (v2 == v1f && i2 < i1)) { sv[tid] = v2; si[tid] = i2; }
          }
          __syncthreads();
        }
        if (tid == 0) {
          int idx = si[0];
          float lp = (g_logits[row * VV + idx] - M) - L;
          g_sampled[row] = idx;
          out[row * SS + t] = (float)idx;
          out[OUT_LP_OFF + row * SS + t] = lp;
        }
        __syncthreads();
      }
    }
    gridbar(bar_target);
  }
}

// ---------------- launch ----------------
extern "C" void kernel_launch(void *const *d_in, const int *in_sizes, int n_in,
                              void *d_out, int out_size) {
  const float *embedding = (const float *)d_in[0];  // [V,E]
  const float *w_ih      = (const float *)d_in[1];  // [3H,E]
  const float *w_hh      = (const float *)d_in[2];  // [3H,H]
  const float *b_ih      = (const float *)d_in[3];  // [3H]
  const float *b_hh      = (const float *)d_in[4];  // [3H]
  const float *w_out     = (const float *)d_in[5];  // [V,H]
  const float *b_out     = (const float *)d_in[6];  // [V]
  float *out = (float *)d_out;

  init_kernel<<<512, 512>>>();
  actor_kernel<<<NBLK, NTHR>>>(embedding, w_ih, w_hh, b_ih, b_hh,
                               w_out, b_out, out);
}